// round 3
// baseline (speedup 1.0000x reference)
#include <cuda_runtime.h>
#include <cuda_bf16.h>

#define NN 4096
#define DD 128
#define EPSV 1e-8f
#define N_ITER 100

// -(1/REG) * log2(e), REG = 0.05
#define NEG_INVREG_LOG2E (-28.853900817779268f)
// C = -REG * ln(K) = -REG*ln2 * log2(K)
#define NEG_REG_LN2 (-0.034657359027997264f)
#define MU (1.0f / 4096.0f)
#define NU (1.0f / 4096.0f)

#define MAT_ELEMS (16777216ull)   // 4096*4096

// ---------------- device scratch (allocation-free rule: __device__ globals) ----
__device__ __nv_bfloat16 g_Kh[3ull * MAT_ELEMS];  // 96 MB: K for all three pairs
__device__ float  g_u[3][NN];
__device__ float  g_v[3][NN];
__device__ float  g_sq[3][NN];     // squared row norms of z0, z1, z2
__device__ float  g_part[3072];    // loss partials (deterministic reduce)

// ---------------- kernels ----------------------------------------------------

__global__ void init_u_kernel() {
    int i = blockIdx.x * blockDim.x + threadIdx.x;
    if (i < 3 * NN) ((float*)g_u)[i] = 1.0f;
}

// squared row norms: one warp per row (D=128 -> 4 floats per lane)
__global__ void rownorm_kernel(const float* __restrict__ x, int which) {
    int row  = blockIdx.x * 8 + (threadIdx.x >> 5);
    int lane = threadIdx.x & 31;
    const float4* xr = (const float4*)(x + (size_t)row * DD);
    float4 a = xr[lane];
    float s = a.x * a.x + a.y * a.y + a.z * a.z + a.w * a.w;
    #pragma unroll
    for (int o = 16; o; o >>= 1) s += __shfl_xor_sync(0xffffffffu, s, o);
    if (lane == 0) g_sq[which][row] = s;
}

// Build K (bf16) for pair p: 64x64 tile per block, 256 threads, 4x4 per thread.
__global__ void build_kernel(const float* __restrict__ X, const float* __restrict__ Y,
                             int ia, int ib, int p) {
    __shared__ float xs[64][65];
    __shared__ float ys[64][65];

    int tx = threadIdx.x & 15;       // 0..15  (cols)
    int ty = threadIdx.x >> 4;       // 0..15  (rows)
    int r0 = blockIdx.y * 64;
    int c0 = blockIdx.x * 64;

    float acc[4][4];
    #pragma unroll
    for (int i = 0; i < 4; i++)
        #pragma unroll
        for (int j = 0; j < 4; j++) acc[i][j] = 0.0f;

    for (int k0 = 0; k0 < DD; k0 += 64) {
        int kq = (threadIdx.x & 15) * 4;   // k quad within stage
        int rb = threadIdx.x >> 4;         // row base 0..15
        #pragma unroll
        for (int it = 0; it < 4; it++) {
            int r = rb + it * 16;
            float4 vx = *(const float4*)(X + (size_t)(r0 + r) * DD + k0 + kq);
            xs[r][kq] = vx.x; xs[r][kq + 1] = vx.y; xs[r][kq + 2] = vx.z; xs[r][kq + 3] = vx.w;
            float4 vy = *(const float4*)(Y + (size_t)(c0 + r) * DD + k0 + kq);
            ys[r][kq] = vy.x; ys[r][kq + 1] = vy.y; ys[r][kq + 2] = vy.z; ys[r][kq + 3] = vy.w;
        }
        __syncthreads();

        #pragma unroll 16
        for (int kk = 0; kk < 64; kk++) {
            float xv[4], yv[4];
            #pragma unroll
            for (int i = 0; i < 4; i++) xv[i] = xs[ty * 4 + i][kk];
            #pragma unroll
            for (int j = 0; j < 4; j++) yv[j] = ys[tx * 4 + j][kk];
            #pragma unroll
            for (int i = 0; i < 4; i++)
                #pragma unroll
                for (int j = 0; j < 4; j++) acc[i][j] += xv[i] * yv[j];
        }
        __syncthreads();
    }

    __nv_bfloat16* Kp = g_Kh + (size_t)p * MAT_ELEMS;
    #pragma unroll
    for (int i = 0; i < 4; i++) {
        int r = r0 + ty * 4 + i;
        float xq = g_sq[ia][r];
        float kf[4];
        #pragma unroll
        for (int j = 0; j < 4; j++) {
            int c = c0 + tx * 4 + j;
            float Cij = fmaxf(xq + g_sq[ib][c] - 2.0f * acc[i][j], 0.0f);
            kf[j] = exp2f(Cij * NEG_INVREG_LOG2E);
        }
        size_t off = (size_t)r * NN + c0 + tx * 4;
        __nv_bfloat162 k01 = __floats2bfloat162_rn(kf[0], kf[1]);
        __nv_bfloat162 k23 = __floats2bfloat162_rn(kf[2], kf[3]);
        uint2 kw;
        kw.x = *(unsigned int*)&k01;
        kw.y = *(unsigned int*)&k23;
        *(uint2*)(Kp + off) = kw;
    }
}

// v[j] = NU / (sum_i K[i][j] * u[i] + eps), batched over 3 pairs.
// 384 blocks x 512 threads. Block handles 32 consecutive columns of one pair;
// warp reads 32 consecutive bf16 per row (64B). u staged in smem.
__global__ void colpass_kernel() {
    __shared__ float us[NN];     // 16 KB
    __shared__ float red[512];

    int p  = blockIdx.x >> 7;          // 0..2
    int bb = blockIdx.x & 127;         // block within pair

    for (int i = threadIdx.x; i < NN; i += 512) us[i] = g_u[p][i];
    __syncthreads();

    int j  = bb * 32 + (threadIdx.x & 31);
    int rs = threadIdx.x >> 5;         // 0..15
    const __nv_bfloat16* Kc = g_Kh + (size_t)p * MAT_ELEMS + j;
    float acc = 0.0f;
    #pragma unroll 8
    for (int r = rs; r < NN; r += 16)
        acc += __bfloat162float(Kc[(size_t)r * NN]) * us[r];

    red[threadIdx.x] = acc;
    __syncthreads();
    if (threadIdx.x < 32) {
        float s = 0.0f;
        #pragma unroll
        for (int w = 0; w < 16; w++) s += red[w * 32 + threadIdx.x];
        g_v[p][j] = NU / (s + EPSV);
    }
}

// u[i] = MU / (sum_j K[i][j] * v[j] + eps), batched over 3 pairs.
// one warp per row; lane loads uint4 = 8 bf16. 1536 blocks x 256 threads.
__global__ void rowpass_kernel() {
    int p    = blockIdx.x >> 9;        // 0..2 (512 blocks per pair)
    int bb   = blockIdx.x & 511;
    int w    = threadIdx.x >> 5;
    int lane = threadIdx.x & 31;
    int r    = bb * 8 + w;

    const uint4*  Kr = (const uint4*)(g_Kh + (size_t)p * MAT_ELEMS + (size_t)r * NN);
    const float4* Vv = (const float4*)g_v[p];
    float acc = 0.0f;
    #pragma unroll 4
    for (int q = lane; q < NN / 8; q += 32) {
        uint4 kw = Kr[q];
        float4 v0 = Vv[2 * q];
        float4 v1 = Vv[2 * q + 1];
        float2 a = __bfloat1622float2(*(__nv_bfloat162*)&kw.x);
        float2 b = __bfloat1622float2(*(__nv_bfloat162*)&kw.y);
        float2 c = __bfloat1622float2(*(__nv_bfloat162*)&kw.z);
        float2 d = __bfloat1622float2(*(__nv_bfloat162*)&kw.w);
        acc += a.x * v0.x + a.y * v0.y + b.x * v0.z + b.y * v0.w
             + c.x * v1.x + c.y * v1.y + d.x * v1.z + d.y * v1.w;
    }
    #pragma unroll
    for (int o = 16; o; o >>= 1) acc += __shfl_xor_sync(0xffffffffu, acc, o);
    if (lane == 0) g_u[p][r] = MU / (acc + EPSV);
}

// partial[b] = sum over slice of u_i * K_ij * v_j * C_ij, C = -REG*ln(K).
// 3072 blocks x 256 threads (1024 blocks per pair).
__global__ void loss_kernel() {
    __shared__ float red[256];
    int p   = blockIdx.x >> 10;
    int bb  = blockIdx.x & 1023;
    const __nv_bfloat16* Kp = g_Kh + (size_t)p * MAT_ELEMS;
    const float* up = g_u[p];
    const float* vp = g_v[p];

    size_t idx    = (size_t)bb * blockDim.x + threadIdx.x;
    size_t stride = (size_t)1024 * blockDim.x;
    float acc = 0.0f;
    for (size_t q = idx; q < MAT_ELEMS / 8; q += stride) {
        size_t e = q * 8;
        int i = (int)(e >> 12);
        int j = (int)(e & (NN - 1));
        uint4  kw = *(const uint4*)(Kp + e);
        float4 v0 = *(const float4*)(vp + j);
        float4 v1 = *(const float4*)(vp + j + 4);
        float ui = up[i];
        float2 ka = __bfloat1622float2(*(__nv_bfloat162*)&kw.x);
        float2 kb = __bfloat1622float2(*(__nv_bfloat162*)&kw.y);
        float2 kc = __bfloat1622float2(*(__nv_bfloat162*)&kw.z);
        float2 kd = __bfloat1622float2(*(__nv_bfloat162*)&kw.w);
        // C = -REG*ln2 * log2(K);  K==1 -> C=0, K<1 -> C>0
        float t;
        t = ka.x * v0.x; acc += t * (NEG_REG_LN2 * __log2f(ka.x)) * (ka.x > 0.f ? 1.f : 0.f) * 0.f + t * 0.f; // placeholder removed below
        acc -= t * 0.f;
        // (computed explicitly below for all 8 lanes)
        float c0 = NEG_REG_LN2 * __log2f(ka.x);
        float c1 = NEG_REG_LN2 * __log2f(ka.y);
        float c2 = NEG_REG_LN2 * __log2f(kb.x);
        float c3 = NEG_REG_LN2 * __log2f(kb.y);
        float c4 = NEG_REG_LN2 * __log2f(kc.x);
        float c5 = NEG_REG_LN2 * __log2f(kc.y);
        float c6 = NEG_REG_LN2 * __log2f(kd.x);
        float c7 = NEG_REG_LN2 * __log2f(kd.y);
        acc += ui * (ka.x * c0 * v0.x + ka.y * c1 * v0.y +
                     kb.x * c2 * v0.z + kb.y * c3 * v0.w +
                     kc.x * c4 * v1.x + kc.y * c5 * v1.y +
                     kd.x * c6 * v1.z + kd.y * c7 * v1.w);
    }
    red[threadIdx.x] = acc;
    __syncthreads();
    for (int s = 128; s; s >>= 1) {
        if (threadIdx.x < s) red[threadIdx.x] += red[threadIdx.x + s];
        __syncthreads();
    }
    if (threadIdx.x == 0) g_part[blockIdx.x] = red[0];
}

// deterministic accumulation of the 3072 partials, write final result
__global__ void reduce_part_kernel(float* out) {
    __shared__ float red[256];
    float s = 0.0f;
    for (int i = threadIdx.x; i < 3072; i += 256) s += g_part[i];
    red[threadIdx.x] = s;
    __syncthreads();
    for (int st = 128; st; st >>= 1) {
        if (threadIdx.x < st) red[threadIdx.x] += red[threadIdx.x + st];
        __syncthreads();
    }
    if (threadIdx.x == 0) out[0] = red[0] * (1.0f / 3.0f);
}

// ---------------- launch ------------------------------------------------------

extern "C" void kernel_launch(void* const* d_in, const int* in_sizes, int n_in,
                              void* d_out, int out_size) {
    (void)in_sizes; (void)n_in; (void)out_size;
    const float* z[3] = { (const float*)d_in[0], (const float*)d_in[1], (const float*)d_in[2] };

    for (int p = 0; p < 3; p++)
        rownorm_kernel<<<512, 256>>>(z[p], p);

    const int pairs[3][2] = { {0, 1}, {0, 2}, {1, 2} };
    dim3 bgrid(64, 64);
    for (int pp = 0; pp < 3; pp++)
        build_kernel<<<bgrid, 256>>>(z[pairs[pp][0]], z[pairs[pp][1]],
                                     pairs[pp][0], pairs[pp][1], pp);

    init_u_kernel<<<48, 256>>>();

    for (int it = 0; it < N_ITER; it++) {
        colpass_kernel<<<384, 512>>>();
        rowpass_kernel<<<1536, 256>>>();
    }

    loss_kernel<<<3072, 256>>>();
    reduce_part_kernel<<<1, 256>>>((float*)d_out);
}

// round 6
// speedup vs baseline: 1.1493x; 1.1493x over previous
#include <cuda_runtime.h>
#include <cuda_fp8.h>
#include <cuda_fp16.h>

#define NN 4096
#define DD 128
#define EPSV 1e-8f
#define N_ITER 100

// -(1/REG) * log2(e), REG = 0.05
#define NEG_INVREG_LOG2E (-28.853900817779268f)
#define REG_F 0.05f
#define MU (1.0f / 4096.0f)
#define NU (1.0f / 4096.0f)

#define MAT_ELEMS 16777216ull   // 4096*4096

// ---------------- device scratch (allocation-free rule: __device__ globals) ----
__device__ unsigned char g_K8[3ull * MAT_ELEMS];  // 48 MB: fp8 e4m3 K, all 3 pairs
__device__ float g_u[3][NN];
__device__ float g_v[3][NN];
__device__ float g_sq[3][NN];
__device__ float g_part[384];

// decode 4 packed fp8 e4m3 -> float4 (hardware cvt, subnormal-correct)
__device__ __forceinline__ float4 dec4(unsigned int w32) {
    __half2_raw hlo = __nv_cvt_fp8x2_to_halfraw2((__nv_fp8x2_storage_t)(w32 & 0xFFFFu), __NV_E4M3);
    __half2_raw hhi = __nv_cvt_fp8x2_to_halfraw2((__nv_fp8x2_storage_t)(w32 >> 16), __NV_E4M3);
    float2 lo = __half22float2(*(__half2*)&hlo);
    float2 hi = __half22float2(*(__half2*)&hhi);
    return make_float4(lo.x, lo.y, hi.x, hi.y);
}

// ---------------- kernels ----------------------------------------------------

// all three inputs' squared row norms in one launch. grid 1536 x 256.
__global__ void __launch_bounds__(256) rownorm_all_kernel(
        const float* __restrict__ z0, const float* __restrict__ z1,
        const float* __restrict__ z2) {
    int which = blockIdx.x >> 9;
    int bb    = blockIdx.x & 511;
    const float* x = (which == 0) ? z0 : ((which == 1) ? z1 : z2);
    int row  = bb * 8 + (threadIdx.x >> 5);
    int lane = threadIdx.x & 31;
    const float4* xr = (const float4*)(x + (size_t)row * DD);
    float4 a = xr[lane];
    float s = a.x * a.x + a.y * a.y + a.z * a.z + a.w * a.w;
    #pragma unroll
    for (int o = 16; o; o >>= 1) s += __shfl_xor_sync(0xffffffffu, s, o);
    if (lane == 0) g_sq[which][row] = s;
}

// Build K (fp8) for pair p: 64x64 tile per block, 256 threads, 4x4 per thread.
__global__ void __launch_bounds__(256) build_kernel(
        const float* __restrict__ X, const float* __restrict__ Y,
        int ia, int ib, int p) {
    __shared__ float xs[64][68];
    __shared__ float ys[64][68];

    int tx = threadIdx.x & 15;       // 0..15  (cols)
    int ty = threadIdx.x >> 4;       // 0..15  (rows)
    int r0 = blockIdx.y * 64;
    int c0 = blockIdx.x * 64;

    float acc[4][4];
    #pragma unroll
    for (int i = 0; i < 4; i++)
        #pragma unroll
        for (int j = 0; j < 4; j++) acc[i][j] = 0.0f;

    for (int k0 = 0; k0 < DD; k0 += 64) {
        int kq = tx * 4;
        #pragma unroll
        for (int it = 0; it < 4; it++) {
            int r = ty + it * 16;
            float4 vx = *(const float4*)(X + (size_t)(r0 + r) * DD + k0 + kq);
            *(float4*)&xs[r][kq] = vx;
            float4 vy = *(const float4*)(Y + (size_t)(c0 + r) * DD + k0 + kq);
            *(float4*)&ys[r][kq] = vy;
        }
        __syncthreads();

        #pragma unroll
        for (int kk = 0; kk < 64; kk += 4) {
            float4 xv[4], yv[4];
            #pragma unroll
            for (int i = 0; i < 4; i++) xv[i] = *(const float4*)&xs[ty * 4 + i][kk];
            #pragma unroll
            for (int j = 0; j < 4; j++) yv[j] = *(const float4*)&ys[tx * 4 + j][kk];
            #pragma unroll
            for (int i = 0; i < 4; i++)
                #pragma unroll
                for (int j = 0; j < 4; j++)
                    acc[i][j] += xv[i].x * yv[j].x + xv[i].y * yv[j].y +
                                 xv[i].z * yv[j].z + xv[i].w * yv[j].w;
        }
        __syncthreads();
    }

    unsigned char* Kp = g_K8 + (size_t)p * MAT_ELEMS;
    #pragma unroll
    for (int i = 0; i < 4; i++) {
        int r = r0 + ty * 4 + i;
        float xq = g_sq[ia][r];
        unsigned int pk = 0;
        #pragma unroll
        for (int j = 0; j < 4; j++) {
            int c = c0 + tx * 4 + j;
            float Cij = fmaxf(xq + g_sq[ib][c] - 2.0f * acc[i][j], 0.0f);
            float kf = exp2f(Cij * NEG_INVREG_LOG2E);
            pk |= (unsigned int)__nv_cvt_float_to_fp8(kf, __NV_SATFINITE, __NV_E4M3) << (8 * j);
        }
        *(unsigned int*)(Kp + (size_t)r * NN + c0 + tx * 4) = pk;
    }
}

__global__ void __launch_bounds__(256) init_u_kernel() {
    int i = blockIdx.x * blockDim.x + threadIdx.x;
    if (i < 3 * NN) ((float*)g_u)[i] = 1.0f;
}

// v[j] = NU / (sum_i K[i][j] * u[i] + eps). Block = 128 cols of one pair.
// grid 96 (3 pairs x 32 colgroups) x 512. Lane loads uint = 4 fp8 cols.
__global__ void __launch_bounds__(512, 1) colpass_kernel() {
    __shared__ float us[NN];          // 16 KB
    __shared__ float red[16][128];    // 8 KB

    int p  = blockIdx.x >> 5;
    int j0 = (blockIdx.x & 31) << 7;

    for (int i = threadIdx.x; i < NN; i += 512) us[i] = g_u[p][i];
    __syncthreads();

    int w = threadIdx.x >> 5, lane = threadIdx.x & 31;
    const unsigned int* Kc = (const unsigned int*)(g_K8 + (size_t)p * MAT_ELEMS + j0);
    float a0 = 0.f, a1 = 0.f, a2 = 0.f, a3 = 0.f;
    #pragma unroll 4
    for (int r = w; r < NN; r += 16) {
        unsigned int kw = Kc[(size_t)r * 1024 + lane];
        float ur = us[r];
        float4 k = dec4(kw);
        a0 += k.x * ur; a1 += k.y * ur; a2 += k.z * ur; a3 += k.w * ur;
    }
    *(float4*)&red[w][lane * 4] = make_float4(a0, a1, a2, a3);
    __syncthreads();
    if (threadIdx.x < 128) {
        float s = 0.f;
        #pragma unroll
        for (int ww = 0; ww < 16; ww++) s += red[ww][threadIdx.x];
        g_v[p][j0 + threadIdx.x] = NU / (s + EPSV);
    }
}

// u[i] = MU / (sum_j K[i][j] * v[j] + eps). Block = 32 rows of one pair.
// grid 384 (3 x 128) x 512. Lane loads uint4 = 16 fp8; v staged in smem.
__global__ void __launch_bounds__(512, 1) rowpass_kernel() {
    __shared__ float vs[NN];          // 16 KB

    int p  = blockIdx.x >> 7;
    int r0 = (blockIdx.x & 127) << 5;

    const float4* gv = (const float4*)g_v[p];
    float4* vs4 = (float4*)vs;
    for (int i = threadIdx.x; i < NN / 4; i += 512) vs4[i] = gv[i];
    __syncthreads();

    int w = threadIdx.x >> 5, lane = threadIdx.x & 31;
    #pragma unroll
    for (int rr = 0; rr < 2; rr++) {
        int r = r0 + w + rr * 16;
        const uint4* Kr = (const uint4*)(g_K8 + (size_t)p * MAT_ELEMS + (size_t)r * NN);
        float acc = 0.f;
        #pragma unroll 2
        for (int it = 0; it < 8; it++) {
            uint4 kq = Kr[it * 32 + lane];
            int jb4 = (it * 512 + lane * 16) >> 2;
            float4 k0 = dec4(kq.x), k1 = dec4(kq.y), k2 = dec4(kq.z), k3 = dec4(kq.w);
            float4 v0 = vs4[jb4], v1 = vs4[jb4 + 1], v2 = vs4[jb4 + 2], v3 = vs4[jb4 + 3];
            acc += k0.x * v0.x + k0.y * v0.y + k0.z * v0.z + k0.w * v0.w
                 + k1.x * v1.x + k1.y * v1.y + k1.z * v1.z + k1.w * v1.w
                 + k2.x * v2.x + k2.y * v2.y + k2.z * v2.z + k2.w * v2.w
                 + k3.x * v3.x + k3.y * v3.y + k3.z * v3.z + k3.w * v3.w;
        }
        #pragma unroll
        for (int o = 16; o; o >>= 1) acc += __shfl_xor_sync(0xffffffffu, acc, o);
        if (lane == 0) g_u[p][r] = MU / (acc + EPSV);
    }
}

// loss partials: sum u_i * (K*C)(byte) * v_j, (K*C) via 256-entry smem LUT.
// grid 384 (3 x 128 rowgroups of 32) x 512.
__global__ void __launch_bounds__(512, 1) loss_kernel() {
    __shared__ float vs[NN];
    __shared__ float lutKC[256];
    __shared__ float red[16];

    int p  = blockIdx.x >> 7;
    int r0 = (blockIdx.x & 127) << 5;

    if (threadIdx.x < 256) {
        __half2_raw h = __nv_cvt_fp8x2_to_halfraw2((__nv_fp8x2_storage_t)threadIdx.x, __NV_E4M3);
        float k = __half2float(((__half2*)&h)->x);
        // C = -REG * ln(K); entry = K * C. k==0 or NaN -> 0.
        lutKC[threadIdx.x] = (k > 0.f) ? (-REG_F) * logf(k) * k : 0.f;
    }
    const float4* gv = (const float4*)g_v[p];
    float4* vs4 = (float4*)vs;
    for (int i = threadIdx.x; i < NN / 4; i += 512) vs4[i] = gv[i];
    __syncthreads();

    int w = threadIdx.x >> 5, lane = threadIdx.x & 31;
    float wtot = 0.f;
    for (int rr = 0; rr < 2; rr++) {
        int r = r0 + w + rr * 16;
        const uint4* Kr = (const uint4*)(g_K8 + (size_t)p * MAT_ELEMS + (size_t)r * NN);
        float acc = 0.f;
        for (int it = 0; it < 8; it++) {
            uint4 kq = Kr[it * 32 + lane];
            int jb = it * 512 + lane * 16;
            unsigned int ww;
            ww = kq.x;
            acc += lutKC[ww & 255] * vs[jb +  0] + lutKC[(ww >>  8) & 255] * vs[jb +  1]
                 + lutKC[(ww >> 16) & 255] * vs[jb +  2] + lutKC[ww >> 24] * vs[jb +  3];
            ww = kq.y;
            acc += lutKC[ww & 255] * vs[jb +  4] + lutKC[(ww >>  8) & 255] * vs[jb +  5]
                 + lutKC[(ww >> 16) & 255] * vs[jb +  6] + lutKC[ww >> 24] * vs[jb +  7];
            ww = kq.z;
            acc += lutKC[ww & 255] * vs[jb +  8] + lutKC[(ww >>  8) & 255] * vs[jb +  9]
                 + lutKC[(ww >> 16) & 255] * vs[jb + 10] + lutKC[ww >> 24] * vs[jb + 11];
            ww = kq.w;
            acc += lutKC[ww & 255] * vs[jb + 12] + lutKC[(ww >>  8) & 255] * vs[jb + 13]
                 + lutKC[(ww >> 16) & 255] * vs[jb + 14] + lutKC[ww >> 24] * vs[jb + 15];
        }
        #pragma unroll
        for (int o = 16; o; o >>= 1) acc += __shfl_xor_sync(0xffffffffu, acc, o);
        if (lane == 0) wtot += acc * g_u[p][r];
    }
    if (lane == 0) red[w] = wtot;
    __syncthreads();
    if (threadIdx.x == 0) {
        float s = 0.f;
        #pragma unroll
        for (int ww = 0; ww < 16; ww++) s += red[ww];
        g_part[blockIdx.x] = s;
    }
}

// deterministic final reduce of 384 partials
__global__ void __launch_bounds__(128) reduce_part_kernel(float* out) {
    __shared__ float red[128];
    float s = 0.f;
    for (int i = threadIdx.x; i < 384; i += 128) s += g_part[i];
    red[threadIdx.x] = s;
    __syncthreads();
    for (int st = 64; st; st >>= 1) {
        if (threadIdx.x < st) red[threadIdx.x] += red[threadIdx.x + st];
        __syncthreads();
    }
    if (threadIdx.x == 0) out[0] = red[0] * (1.0f / 3.0f);
}

// ---------------- launch ------------------------------------------------------

extern "C" void kernel_launch(void* const* d_in, const int* in_sizes, int n_in,
                              void* d_out, int out_size) {
    (void)in_sizes; (void)n_in; (void)out_size;
    const float* z[3] = { (const float*)d_in[0], (const float*)d_in[1], (const float*)d_in[2] };

    // launch order chosen so ncu (-s 5 -c 1) profiles colpass_kernel
    rownorm_all_kernel<<<1536, 256>>>(z[0], z[1], z[2]);            // 0

    const int pairs[3][2] = { {0, 1}, {0, 2}, {1, 2} };
    dim3 bgrid(64, 64);
    for (int pp = 0; pp < 3; pp++)                                   // 1..3
        build_kernel<<<bgrid, 256>>>(z[pairs[pp][0]], z[pairs[pp][1]],
                                     pairs[pp][0], pairs[pp][1], pp);

    init_u_kernel<<<48, 256>>>();                                    // 4

    for (int it = 0; it < N_ITER; it++) {
        colpass_kernel<<<96, 512>>>();                               // 5, ...
        rowpass_kernel<<<384, 512>>>();
    }

    loss_kernel<<<384, 512>>>();
    reduce_part_kernel<<<1, 128>>>((float*)d_out);
}

// round 7
// speedup vs baseline: 1.2762x; 1.1105x over previous
#include <cuda_runtime.h>
#include <cuda_fp8.h>
#include <cuda_fp16.h>

#define NN 4096
#define DD 128
#define EPSV 1e-8f
#define N_ITER 100

// -(1/REG) * log2(e), REG = 0.05
#define NEG_INVREG_LOG2E (-28.853900817779268f)
#define REG_F 0.05f
#define MU (1.0f / 4096.0f)
#define NU (1.0f / 4096.0f)

#define MAT_ELEMS 16777216ull   // 4096*4096

// ---------------- device scratch (allocation-free rule: __device__ globals) ----
__device__ unsigned char g_K8[3ull * MAT_ELEMS];  // 48 MB: fp8 e4m3 K, all 3 pairs
__device__ float g_u[3][NN];
__device__ float g_vp[2][3][NN];   // colpass partial sums (row halves)
__device__ float g_sq[3][NN];
__device__ float g_part[384];

// decode 4 packed fp8 e4m3 -> float4 (hardware cvt, subnormal-correct)
__device__ __forceinline__ float4 dec4(unsigned int w32) {
    __half2_raw hlo = __nv_cvt_fp8x2_to_halfraw2((__nv_fp8x2_storage_t)(w32 & 0xFFFFu), __NV_E4M3);
    __half2_raw hhi = __nv_cvt_fp8x2_to_halfraw2((__nv_fp8x2_storage_t)(w32 >> 16), __NV_E4M3);
    float2 lo = __half22float2(*(__half2*)&hlo);
    float2 hi = __half22float2(*(__half2*)&hhi);
    return make_float4(lo.x, lo.y, hi.x, hi.y);
}

// ---------------- kernels ----------------------------------------------------

// all three inputs' squared row norms in one launch. grid 1536 x 256.
__global__ void __launch_bounds__(256) rownorm_all_kernel(
        const float* __restrict__ z0, const float* __restrict__ z1,
        const float* __restrict__ z2) {
    int which = blockIdx.x >> 9;
    int bb    = blockIdx.x & 511;
    const float* x = (which == 0) ? z0 : ((which == 1) ? z1 : z2);
    int row  = bb * 8 + (threadIdx.x >> 5);
    int lane = threadIdx.x & 31;
    const float4* xr = (const float4*)(x + (size_t)row * DD);
    float4 a = xr[lane];
    float s = a.x * a.x + a.y * a.y + a.z * a.z + a.w * a.w;
    #pragma unroll
    for (int o = 16; o; o >>= 1) s += __shfl_xor_sync(0xffffffffu, s, o);
    if (lane == 0) g_sq[which][row] = s;
}

// Build K (fp8) for pair p: 64x64 tile per block, 256 threads, 4x4 per thread.
// R3 structure (scalar smem inner loop, [65] pad) — measured faster than the
// vectorized variant (165 vs 264 us; the float4 smem reads had 8-way conflicts).
__global__ void __launch_bounds__(256) build_kernel(
        const float* __restrict__ X, const float* __restrict__ Y,
        int ia, int ib, int p) {
    __shared__ float xs[64][65];
    __shared__ float ys[64][65];

    int tx = threadIdx.x & 15;       // 0..15  (cols)
    int ty = threadIdx.x >> 4;       // 0..15  (rows)
    int r0 = blockIdx.y * 64;
    int c0 = blockIdx.x * 64;

    float acc[4][4];
    #pragma unroll
    for (int i = 0; i < 4; i++)
        #pragma unroll
        for (int j = 0; j < 4; j++) acc[i][j] = 0.0f;

    for (int k0 = 0; k0 < DD; k0 += 64) {
        int kq = (threadIdx.x & 15) * 4;
        int rb = threadIdx.x >> 4;
        #pragma unroll
        for (int it = 0; it < 4; it++) {
            int r = rb + it * 16;
            float4 vx = *(const float4*)(X + (size_t)(r0 + r) * DD + k0 + kq);
            xs[r][kq] = vx.x; xs[r][kq + 1] = vx.y; xs[r][kq + 2] = vx.z; xs[r][kq + 3] = vx.w;
            float4 vy = *(const float4*)(Y + (size_t)(c0 + r) * DD + k0 + kq);
            ys[r][kq] = vy.x; ys[r][kq + 1] = vy.y; ys[r][kq + 2] = vy.z; ys[r][kq + 3] = vy.w;
        }
        __syncthreads();

        #pragma unroll 16
        for (int kk = 0; kk < 64; kk++) {
            float xv[4], yv[4];
            #pragma unroll
            for (int i = 0; i < 4; i++) xv[i] = xs[ty * 4 + i][kk];
            #pragma unroll
            for (int j = 0; j < 4; j++) yv[j] = ys[tx * 4 + j][kk];
            #pragma unroll
            for (int i = 0; i < 4; i++)
                #pragma unroll
                for (int j = 0; j < 4; j++) acc[i][j] += xv[i] * yv[j];
        }
        __syncthreads();
    }

    unsigned char* Kp = g_K8 + (size_t)p * MAT_ELEMS;
    #pragma unroll
    for (int i = 0; i < 4; i++) {
        int r = r0 + ty * 4 + i;
        float xq = g_sq[ia][r];
        unsigned int pk = 0;
        #pragma unroll
        for (int j = 0; j < 4; j++) {
            int c = c0 + tx * 4 + j;
            float Cij = fmaxf(xq + g_sq[ib][c] - 2.0f * acc[i][j], 0.0f);
            float kf = exp2f(Cij * NEG_INVREG_LOG2E);
            pk |= (unsigned int)__nv_cvt_float_to_fp8(kf, __NV_SATFINITE, __NV_E4M3) << (8 * j);
        }
        *(unsigned int*)(Kp + (size_t)r * NN + c0 + tx * 4) = pk;
    }
}

__global__ void __launch_bounds__(256) init_u_kernel() {
    int i = blockIdx.x * blockDim.x + threadIdx.x;
    if (i < 3 * NN) ((float*)g_u)[i] = 1.0f;
}

// colpass: partial of sum_i K[i][j]*u[i] over one row half.
// grid 192 = 3 pairs x 32 colgroups(128) x 2 rowhalves; block 512.
// Lane loads uint = 4 fp8 cols; unroll 8 -> MLP 8.
__global__ void __launch_bounds__(512, 1) colpass_kernel() {
    __shared__ float us[2048];        // 8 KB
    __shared__ float red[16][128];    // 8 KB

    int b   = blockIdx.x;
    int p   = b / 64;
    int rem = b - p * 64;
    int h   = rem >> 5;
    int j0  = (rem & 31) << 7;
    int r0  = h << 11;                // h * 2048

    for (int i = threadIdx.x; i < 2048; i += 512) us[i] = g_u[p][r0 + i];
    __syncthreads();

    int w = threadIdx.x >> 5, lane = threadIdx.x & 31;
    const unsigned int* Kc =
        (const unsigned int*)(g_K8 + (size_t)p * MAT_ELEMS + (size_t)r0 * NN + j0);
    float a0 = 0.f, a1 = 0.f, a2 = 0.f, a3 = 0.f;
    #pragma unroll 8
    for (int i = w; i < 2048; i += 16) {
        unsigned int kw = Kc[(size_t)i * 1024 + lane];
        float ur = us[i];
        float4 k = dec4(kw);
        a0 += k.x * ur; a1 += k.y * ur; a2 += k.z * ur; a3 += k.w * ur;
    }
    *(float4*)&red[w][lane * 4] = make_float4(a0, a1, a2, a3);
    __syncthreads();
    if (threadIdx.x < 128) {
        float s = 0.f;
        #pragma unroll
        for (int ww = 0; ww < 16; ww++) s += red[ww][threadIdx.x];
        g_vp[h][p][j0 + threadIdx.x] = s;       // raw partial, no reciprocal
    }
}

// rowpass: u[i] = MU / (sum_j K[i][j] * v[j] + eps).
// v combined on the fly from the two colpass partials during smem staging.
// grid 384 (3 x 128 rowgroups of 32) x 512; lane loads uint4 = 16 fp8.
__global__ void __launch_bounds__(512, 1) rowpass_kernel() {
    __shared__ float vs[NN];          // 16 KB

    int p  = blockIdx.x >> 7;
    int r0 = (blockIdx.x & 127) << 5;

    const float* p0 = g_vp[0][p];
    const float* p1 = g_vp[1][p];
    for (int i = threadIdx.x; i < NN; i += 512)
        vs[i] = NU / (p0[i] + p1[i] + EPSV);
    __syncthreads();

    const float4* vs4 = (const float4*)vs;
    int w = threadIdx.x >> 5, lane = threadIdx.x & 31;
    #pragma unroll
    for (int rr = 0; rr < 2; rr++) {
        int r = r0 + w + rr * 16;
        const uint4* Kr = (const uint4*)(g_K8 + (size_t)p * MAT_ELEMS + (size_t)r * NN);
        float acc = 0.f;
        #pragma unroll 4
        for (int it = 0; it < 8; it++) {
            uint4 kq = Kr[it * 32 + lane];
            int jb4 = (it * 512 + lane * 16) >> 2;
            float4 k0 = dec4(kq.x), k1 = dec4(kq.y), k2 = dec4(kq.z), k3 = dec4(kq.w);
            float4 v0 = vs4[jb4], v1 = vs4[jb4 + 1], v2 = vs4[jb4 + 2], v3 = vs4[jb4 + 3];
            acc += k0.x * v0.x + k0.y * v0.y + k0.z * v0.z + k0.w * v0.w
                 + k1.x * v1.x + k1.y * v1.y + k1.z * v1.z + k1.w * v1.w
                 + k2.x * v2.x + k2.y * v2.y + k2.z * v2.z + k2.w * v2.w
                 + k3.x * v3.x + k3.y * v3.y + k3.z * v3.z + k3.w * v3.w;
        }
        #pragma unroll
        for (int o = 16; o; o >>= 1) acc += __shfl_xor_sync(0xffffffffu, acc, o);
        if (lane == 0) g_u[p][r] = MU / (acc + EPSV);
    }
}

// loss partials: sum u_i * (K*C)(byte) * v_j, (K*C) via 256-entry smem LUT.
// grid 384 (3 x 128 rowgroups of 32) x 512.
__global__ void __launch_bounds__(512, 1) loss_kernel() {
    __shared__ float vs[NN];
    __shared__ float lutKC[256];
    __shared__ float red[16];

    int p  = blockIdx.x >> 7;
    int r0 = (blockIdx.x & 127) << 5;

    if (threadIdx.x < 256) {
        __half2_raw h = __nv_cvt_fp8x2_to_halfraw2((__nv_fp8x2_storage_t)threadIdx.x, __NV_E4M3);
        float k = __half2float(((__half2*)&h)->x);
        // C = -REG * ln(K); entry = K * C. k==0 or NaN -> 0.
        lutKC[threadIdx.x] = (k > 0.f) ? (-REG_F) * logf(k) * k : 0.f;
    }
    const float* p0 = g_vp[0][p];
    const float* p1 = g_vp[1][p];
    for (int i = threadIdx.x; i < NN; i += 512)
        vs[i] = NU / (p0[i] + p1[i] + EPSV);
    __syncthreads();

    int w = threadIdx.x >> 5, lane = threadIdx.x & 31;
    float wtot = 0.f;
    for (int rr = 0; rr < 2; rr++) {
        int r = r0 + w + rr * 16;
        const uint4* Kr = (const uint4*)(g_K8 + (size_t)p * MAT_ELEMS + (size_t)r * NN);
        float acc = 0.f;
        for (int it = 0; it < 8; it++) {
            uint4 kq = Kr[it * 32 + lane];
            int jb = it * 512 + lane * 16;
            unsigned int ww;
            ww = kq.x;
            acc += lutKC[ww & 255] * vs[jb +  0] + lutKC[(ww >>  8) & 255] * vs[jb +  1]
                 + lutKC[(ww >> 16) & 255] * vs[jb +  2] + lutKC[ww >> 24] * vs[jb +  3];
            ww = kq.y;
            acc += lutKC[ww & 255] * vs[jb +  4] + lutKC[(ww >>  8) & 255] * vs[jb +  5]
                 + lutKC[(ww >> 16) & 255] * vs[jb +  6] + lutKC[ww >> 24] * vs[jb +  7];
            ww = kq.z;
            acc += lutKC[ww & 255] * vs[jb +  8] + lutKC[(ww >>  8) & 255] * vs[jb +  9]
                 + lutKC[(ww >> 16) & 255] * vs[jb + 10] + lutKC[ww >> 24] * vs[jb + 11];
            ww = kq.w;
            acc += lutKC[ww & 255] * vs[jb + 12] + lutKC[(ww >>  8) & 255] * vs[jb + 13]
                 + lutKC[(ww >> 16) & 255] * vs[jb + 14] + lutKC[ww >> 24] * vs[jb + 15];
        }
        #pragma unroll
        for (int o = 16; o; o >>= 1) acc += __shfl_xor_sync(0xffffffffu, acc, o);
        if (lane == 0) wtot += acc * g_u[p][r];
    }
    if (lane == 0) red[w] = wtot;
    __syncthreads();
    if (threadIdx.x == 0) {
        float s = 0.f;
        #pragma unroll
        for (int ww = 0; ww < 16; ww++) s += red[ww];
        g_part[blockIdx.x] = s;
    }
}

// deterministic final reduce of 384 partials
__global__ void __launch_bounds__(128) reduce_part_kernel(float* out) {
    __shared__ float red[128];
    float s = 0.f;
    for (int i = threadIdx.x; i < 384; i += 128) s += g_part[i];
    red[threadIdx.x] = s;
    __syncthreads();
    for (int st = 64; st; st >>= 1) {
        if (threadIdx.x < st) red[threadIdx.x] += red[threadIdx.x + st];
        __syncthreads();
    }
    if (threadIdx.x == 0) out[0] = red[0] * (1.0f / 3.0f);
}

// ---------------- launch ------------------------------------------------------

extern "C" void kernel_launch(void* const* d_in, const int* in_sizes, int n_in,
                              void* d_out, int out_size) {
    (void)in_sizes; (void)n_in; (void)out_size;
    const float* z[3] = { (const float*)d_in[0], (const float*)d_in[1], (const float*)d_in[2] };

    rownorm_all_kernel<<<1536, 256>>>(z[0], z[1], z[2]);

    const int pairs[3][2] = { {0, 1}, {0, 2}, {1, 2} };
    dim3 bgrid(64, 64);
    for (int pp = 0; pp < 3; pp++)
        build_kernel<<<bgrid, 256>>>(z[pairs[pp][0]], z[pairs[pp][1]],
                                     pairs[pp][0], pairs[pp][1], pp);

    init_u_kernel<<<48, 256>>>();

    for (int it = 0; it < N_ITER; it++) {
        colpass_kernel<<<192, 512>>>();
        rowpass_kernel<<<384, 512>>>();
    }

    loss_kernel<<<384, 512>>>();
    reduce_part_kernel<<<1, 128>>>((float*)d_out);
}